// round 1
// baseline (speedup 1.0000x reference)
#include <cuda_runtime.h>

#define T_TOK 1024
#define D_DIM 1024
#define F_DIM 2048
#define E_EXP 32
#define TOPK  4
#define NPAIR (T_TOK * TOPK)

// ---------------- scratch (static device globals; no allocs allowed) ----------------
__device__ int   g_cnt[E_EXP];
__device__ int   g_pairs[E_EXP * T_TOK];            // pair id (= tok*4+k) per expert slot
__device__ float g_w[NPAIR];                        // combine weight per pair
__device__ float g_h[(size_t)NPAIR * F_DIM];        // routed hidden (32 MB)
__device__ float g_hs[(size_t)T_TOK * F_DIM];       // shared-expert hidden (8 MB)

// ---------------- tiny kernels ----------------
__global__ void zero_kernel() {
    if (threadIdx.x < E_EXP) g_cnt[threadIdx.x] = 0;
}

__global__ void router_kernel(const float* __restrict__ x,
                              const float* __restrict__ gw,
                              const float* __restrict__ bias) {
    __shared__ float xs[D_DIM];
    __shared__ float logits[E_EXP];
    int t = blockIdx.x;
    const float4* xr = (const float4*)(x + (size_t)t * D_DIM);
    for (int i = threadIdx.x; i < D_DIM / 4; i += blockDim.x)
        ((float4*)xs)[i] = xr[i];
    __syncthreads();

    int e = threadIdx.x >> 2;      // 32 experts * 4 lanes = 128 threads
    int g = threadIdx.x & 3;
    const float4* wrow = (const float4*)(gw + (size_t)e * D_DIM);
    float s = 0.f;
    for (int d4 = g; d4 < D_DIM / 4; d4 += 4) {
        float4 a = ((const float4*)xs)[d4];
        float4 b = wrow[d4];
        s += a.x * b.x + a.y * b.y + a.z * b.z + a.w * b.w;
    }
    s += __shfl_down_sync(0xffffffffu, s, 2, 4);
    s += __shfl_down_sync(0xffffffffu, s, 1, 4);
    if (g == 0) logits[e] = s + bias[e];
    __syncthreads();

    if (threadIdx.x == 0) {
        float v[TOPK]; int idx[TOPK];
        unsigned used = 0;
        for (int k = 0; k < TOPK; k++) {
            float best = -3.4e38f; int bi = 0;
            for (int j = 0; j < E_EXP; j++) {
                if (used & (1u << j)) continue;
                if (logits[j] > best) { best = logits[j]; bi = j; }
            }
            used |= 1u << bi; v[k] = best; idx[k] = bi;
        }
        float ex[TOPK], sum = 0.f;
        for (int k = 0; k < TOPK; k++) { ex[k] = __expf(v[k] - v[0]); sum += ex[k]; }
        float inv = 1.f / sum;
        for (int k = 0; k < TOPK; k++) {
            int ek = idx[k];
            int slot = atomicAdd(&g_cnt[ek], 1);
            g_pairs[ek * T_TOK + slot] = t * TOPK + k;
            g_w[t * TOPK + k] = ex[k] * inv;
        }
    }
}

__global__ void stats_kernel(float* __restrict__ tail) {
    int e = threadIdx.x;      // 32 threads
    float c = (float)g_cnt[e];
    float mean = (float)(T_TOK * TOPK) / E_EXP;   // always 128
    float d = c - mean;
    float v = d * d;
    for (int o = 16; o > 0; o >>= 1) v += __shfl_down_sync(0xffffffffu, v, o);
    if (tail) {
        tail[e] = c;
        if (e == 0) tail[E_EXP] = sqrtf(v / E_EXP) / (mean + 1e-6f);
    }
}

// ---------------- fused gate+up GEMM (NT, both K-major), SiLU epilogue ----------------
// C[m,n] over (rows of x gathered) x (rows of Wg/Wu). BM=BN=64, BK=16, 256 thr, 4x4.
template <bool SHARED>
__global__ __launch_bounds__(256)
void gateup_kernel(const float* __restrict__ x,
                   const float* __restrict__ Wg,
                   const float* __restrict__ Wu) {
    int e  = SHARED ? 0 : blockIdx.z;
    int m0 = blockIdx.y * 64;
    int n0 = blockIdx.x * 64;
    int ne = SHARED ? T_TOK : g_cnt[e];
    if (m0 >= ne) return;

    const float* wg = Wg + (SHARED ? (size_t)0 : (size_t)e * F_DIM * D_DIM);
    const float* wu = Wu + (SHARED ? (size_t)0 : (size_t)e * F_DIM * D_DIM);
    float* H = SHARED ? g_hs : g_h;

    __shared__ float As[16][64];
    __shared__ float Bg[16][64];
    __shared__ float Bu[16][64];
    __shared__ int   rowtok[64];
    __shared__ int   rowpair[64];

    int tid = threadIdx.x;
    if (tid < 64) {
        int m = m0 + tid;
        int pair, tok;
        if (SHARED) { pair = m; tok = m; }
        else {
            pair = (m < ne) ? g_pairs[e * T_TOK + m] : 0;
            tok  = pair >> 2;
        }
        rowtok[tid]  = tok;
        rowpair[tid] = pair;
    }
    __syncthreads();

    int lm = tid >> 2;            // 0..63: tile row for loads
    int lk = (tid & 3) * 4;       // 0,4,8,12: k offset
    int ty = tid >> 4;            // 0..15
    int tx = tid & 15;            // 0..15

    float cg[4][4] = {}, cu[4][4] = {};

    for (int k0 = 0; k0 < D_DIM; k0 += 16) {
        float4 av = *(const float4*)(x  + (size_t)rowtok[lm] * D_DIM + k0 + lk);
        float4 gv = *(const float4*)(wg + (size_t)(n0 + lm) * D_DIM + k0 + lk);
        float4 uv = *(const float4*)(wu + (size_t)(n0 + lm) * D_DIM + k0 + lk);
        __syncthreads();
        As[lk + 0][lm] = av.x; As[lk + 1][lm] = av.y; As[lk + 2][lm] = av.z; As[lk + 3][lm] = av.w;
        Bg[lk + 0][lm] = gv.x; Bg[lk + 1][lm] = gv.y; Bg[lk + 2][lm] = gv.z; Bg[lk + 3][lm] = gv.w;
        Bu[lk + 0][lm] = uv.x; Bu[lk + 1][lm] = uv.y; Bu[lk + 2][lm] = uv.z; Bu[lk + 3][lm] = uv.w;
        __syncthreads();
#pragma unroll
        for (int kk = 0; kk < 16; kk++) {
            float4 a  = *(const float4*)&As[kk][ty * 4];
            float4 bg = *(const float4*)&Bg[kk][tx * 4];
            float4 bu = *(const float4*)&Bu[kk][tx * 4];
            float ar[4] = {a.x, a.y, a.z, a.w};
            float gr[4] = {bg.x, bg.y, bg.z, bg.w};
            float ur[4] = {bu.x, bu.y, bu.z, bu.w};
#pragma unroll
            for (int i = 0; i < 4; i++)
#pragma unroll
                for (int j = 0; j < 4; j++) {
                    cg[i][j] += ar[i] * gr[j];
                    cu[i][j] += ar[i] * ur[j];
                }
        }
    }

#pragma unroll
    for (int i = 0; i < 4; i++) {
        int mr = ty * 4 + i;
        int m  = m0 + mr;
        if (!SHARED && m >= ne) continue;
        int hrow = SHARED ? m : rowpair[mr];
        float4 st;
        float* po = &st.x;
#pragma unroll
        for (int j = 0; j < 4; j++) {
            float gvv = cg[i][j];
            float sg  = 1.f / (1.f + __expf(-gvv));
            po[j] = gvv * sg * cu[i][j];
        }
        *(float4*)(H + (size_t)hrow * F_DIM + n0 + tx * 4) = st;
    }
}

// ---------------- down GEMM: h @ Wd^T ----------------
template <bool SHARED>
__global__ __launch_bounds__(256)
void down_kernel(const float* __restrict__ Wd, float* __restrict__ out) {
    int e  = SHARED ? 0 : blockIdx.z;
    int m0 = blockIdx.y * 64;
    int n0 = blockIdx.x * 64;     // output D-column tile
    int ne = SHARED ? T_TOK : g_cnt[e];
    if (m0 >= ne) return;

    const float* wd  = Wd + (SHARED ? (size_t)0 : (size_t)e * D_DIM * F_DIM);
    const float* Hin = SHARED ? g_hs : g_h;

    __shared__ float As[16][64];
    __shared__ float Bs[16][64];
    __shared__ int   rowpair[64];

    int tid = threadIdx.x;
    if (tid < 64) {
        int m = m0 + tid;
        rowpair[tid] = SHARED ? m : ((m < ne) ? g_pairs[e * T_TOK + m] : 0);
    }
    __syncthreads();

    int lm = tid >> 2;
    int lk = (tid & 3) * 4;
    int ty = tid >> 4;
    int tx = tid & 15;

    float c[4][4] = {};

    for (int k0 = 0; k0 < F_DIM; k0 += 16) {
        float4 av = *(const float4*)(Hin + (size_t)rowpair[lm] * F_DIM + k0 + lk);
        float4 bv = *(const float4*)(wd  + (size_t)(n0 + lm)  * F_DIM + k0 + lk);
        __syncthreads();
        As[lk + 0][lm] = av.x; As[lk + 1][lm] = av.y; As[lk + 2][lm] = av.z; As[lk + 3][lm] = av.w;
        Bs[lk + 0][lm] = bv.x; Bs[lk + 1][lm] = bv.y; Bs[lk + 2][lm] = bv.z; Bs[lk + 3][lm] = bv.w;
        __syncthreads();
#pragma unroll
        for (int kk = 0; kk < 16; kk++) {
            float4 a = *(const float4*)&As[kk][ty * 4];
            float4 b = *(const float4*)&Bs[kk][tx * 4];
            float ar[4] = {a.x, a.y, a.z, a.w};
            float br[4] = {b.x, b.y, b.z, b.w};
#pragma unroll
            for (int i = 0; i < 4; i++)
#pragma unroll
                for (int j = 0; j < 4; j++)
                    c[i][j] += ar[i] * br[j];
        }
    }

#pragma unroll
    for (int i = 0; i < 4; i++) {
        int mr = ty * 4 + i;
        int m  = m0 + mr;
        if (SHARED) {
            float4 st = {c[i][0], c[i][1], c[i][2], c[i][3]};
            *(float4*)(out + (size_t)m * D_DIM + n0 + tx * 4) = st;
        } else {
            if (m >= ne) continue;
            int pair = rowpair[mr];
            int tok  = pair >> 2;
            float w  = g_w[pair];
            float* op = out + (size_t)tok * D_DIM + n0 + tx * 4;
            atomicAdd(op + 0, w * c[i][0]);
            atomicAdd(op + 1, w * c[i][1]);
            atomicAdd(op + 2, w * c[i][2]);
            atomicAdd(op + 3, w * c[i][3]);
        }
    }
}

// ---------------- launch ----------------
extern "C" void kernel_launch(void* const* d_in, const int* in_sizes, int n_in,
                              void* d_out, int out_size) {
    const float* x    = (const float*)d_in[0];
    const float* gw   = (const float*)d_in[1];
    const float* bias = (const float*)d_in[2];
    const float* wg   = (const float*)d_in[3];
    const float* wu   = (const float*)d_in[4];
    const float* wd   = (const float*)d_in[5];
    const float* wsg  = (const float*)d_in[6];
    const float* wsu  = (const float*)d_in[7];
    const float* wsd  = (const float*)d_in[8];
    float* out = (float*)d_out;

    zero_kernel<<<1, 32>>>();
    router_kernel<<<T_TOK, 128>>>(x, gw, bias);

    float* tail = (out_size >= T_TOK * D_DIM + E_EXP + 1) ? (out + T_TOK * D_DIM) : nullptr;
    stats_kernel<<<1, 32>>>(tail);

    // shared expert: full coverage plain-store of `out`
    gateup_kernel<true><<<dim3(F_DIM / 64, T_TOK / 64), 256>>>(x, wsg, wsu);
    down_kernel<true><<<dim3(D_DIM / 64, T_TOK / 64), 256>>>(wsd, out);

    // routed experts: gather rows, fused SiLU, weighted atomic combine
    gateup_kernel<false><<<dim3(F_DIM / 64, T_TOK / 64, E_EXP), 256>>>(x, wg, wu);
    down_kernel<false><<<dim3(D_DIM / 64, T_TOK / 64, E_EXP), 256>>>(wd, out);
}

// round 3
// speedup vs baseline: 2.6535x; 2.6535x over previous
#include <cuda_runtime.h>
#include <cuda_bf16.h>
#include <stdint.h>

#define T_TOK 1024
#define D_DIM 1024
#define F_DIM 2048
#define E_EXP 32
#define TOPK  4
#define NPAIR (T_TOK * TOPK)

// ---------------- static scratch ----------------
__device__ int      g_cnt[E_EXP];
__device__ int      g_pairs[E_EXP * T_TOK];
__device__ float    g_w[NPAIR];
__device__ uint32_t g_hp[(size_t)NPAIR * F_DIM];   // routed hidden, packed bf16 hi|lo<<16 (32MB)
__device__ uint32_t g_hsp[(size_t)T_TOK * F_DIM];  // shared hidden packed (8MB)
__device__ float    g_y[(size_t)NPAIR * D_DIM];    // routed per-pair down output (16MB)

// ---------------- helpers ----------------
__device__ __forceinline__ uint32_t smem_u32(const void* p) {
    uint32_t a;
    asm("{ .reg .u64 t; cvta.to.shared.u64 t, %1; cvt.u32.u64 %0, t; }" : "=r"(a) : "l"(p));
    return a;
}
__device__ __forceinline__ void ldm4(uint32_t* r, uint32_t addr) {
    asm volatile("ldmatrix.sync.aligned.m8n8.x4.shared.b16 {%0,%1,%2,%3}, [%4];"
                 : "=r"(r[0]), "=r"(r[1]), "=r"(r[2]), "=r"(r[3]) : "r"(addr));
}
__device__ __forceinline__ void mma16816(float* d, const uint32_t* a, const uint32_t* b) {
    asm volatile("mma.sync.aligned.m16n8k16.row.col.f32.bf16.bf16.f32 "
                 "{%0,%1,%2,%3}, {%4,%5,%6,%7}, {%8,%9}, {%0,%1,%2,%3};"
                 : "+f"(d[0]), "+f"(d[1]), "+f"(d[2]), "+f"(d[3])
                 : "r"(a[0]), "r"(a[1]), "r"(a[2]), "r"(a[3]), "r"(b[0]), "r"(b[1]));
}
// split two fp32 -> packed hi bf16x2 + packed lo bf16x2 (x0 in low half)
__device__ __forceinline__ void cvt_split(float x0, float x1, uint32_t& hi, uint32_t& lo) {
    asm("cvt.rn.bf16x2.f32 %0, %1, %2;" : "=r"(hi) : "f"(x1), "f"(x0));
    float f0 = __uint_as_float(hi << 16);
    float f1 = __uint_as_float(hi & 0xffff0000u);
    float r0 = x0 - f0, r1 = x1 - f1;
    asm("cvt.rn.bf16x2.f32 %0, %1, %2;" : "=r"(lo) : "f"(r1), "f"(r0));
}
__device__ __forceinline__ void split_store4(char* hi, char* lo, float4 v) {
    uint32_t h0, l0, h1, l1;
    cvt_split(v.x, v.y, h0, l0);
    cvt_split(v.z, v.w, h1, l1);
    *(uint2*)hi = make_uint2(h0, h1);
    *(uint2*)lo = make_uint2(l0, l1);
}
__device__ __forceinline__ uint32_t pack_split1(float h) {
    __nv_bfloat16 hb = __float2bfloat16_rn(h);
    float r = h - __bfloat162float(hb);
    __nv_bfloat16 lb = __float2bfloat16_rn(r);
    return (uint32_t)__bfloat16_as_ushort(hb) | ((uint32_t)__bfloat16_as_ushort(lb) << 16);
}

// ---------------- tiny kernels ----------------
__global__ void zero_kernel() {
    if (threadIdx.x < E_EXP) g_cnt[threadIdx.x] = 0;
}

__global__ void router_kernel(const float* __restrict__ x,
                              const float* __restrict__ gw,
                              const float* __restrict__ bias) {
    __shared__ float xs[D_DIM];
    __shared__ float logits[E_EXP];
    int t = blockIdx.x;
    const float4* xr = (const float4*)(x + (size_t)t * D_DIM);
    for (int i = threadIdx.x; i < D_DIM / 4; i += blockDim.x)
        ((float4*)xs)[i] = xr[i];
    __syncthreads();

    int e = threadIdx.x >> 2;
    int g = threadIdx.x & 3;
    const float4* wrow = (const float4*)(gw + (size_t)e * D_DIM);
    float s = 0.f;
    for (int d4 = g; d4 < D_DIM / 4; d4 += 4) {
        float4 a = ((const float4*)xs)[d4];
        float4 b = wrow[d4];
        s += a.x * b.x + a.y * b.y + a.z * b.z + a.w * b.w;
    }
    s += __shfl_down_sync(0xffffffffu, s, 2, 4);
    s += __shfl_down_sync(0xffffffffu, s, 1, 4);
    if (g == 0) logits[e] = s + bias[e];
    __syncthreads();

    if (threadIdx.x == 0) {
        float v[TOPK]; int idx[TOPK];
        unsigned used = 0;
        for (int k = 0; k < TOPK; k++) {
            float best = -3.4e38f; int bi = 0;
            for (int j = 0; j < E_EXP; j++) {
                if (used & (1u << j)) continue;
                if (logits[j] > best) { best = logits[j]; bi = j; }
            }
            used |= 1u << bi; v[k] = best; idx[k] = bi;
        }
        float ex[TOPK], sum = 0.f;
        for (int k = 0; k < TOPK; k++) { ex[k] = __expf(v[k] - v[0]); sum += ex[k]; }
        float inv = 1.f / sum;
        for (int k = 0; k < TOPK; k++) {
            int ek = idx[k];
            int slot = atomicAdd(&g_cnt[ek], 1);
            g_pairs[ek * T_TOK + slot] = t * TOPK + k;
            g_w[t * TOPK + k] = ex[k] * inv;
        }
    }
}

__global__ void stats_kernel(float* __restrict__ tail) {
    int e = threadIdx.x;
    float c = (float)g_cnt[e];
    float mean = (float)(T_TOK * TOPK) / E_EXP;
    float d = c - mean;
    float v = d * d;
    for (int o = 16; o > 0; o >>= 1) v += __shfl_down_sync(0xffffffffu, v, o);
    if (tail) {
        tail[e] = c;
        if (e == 0) tail[E_EXP] = sqrtf(v / E_EXP) / (mean + 1e-6f);
    }
}

// ================= gate+up warp-MMA kernel =================
// CTA: 128(M) x 64(N of F) for BOTH gate and up. BK=64. 8 warps:
// warps 0-3 gate, 4-7 up, each 64x32 (MT=4, NT=4).
#define APITCH 144             // 64 bf16 + 8 pad, bytes
#define GU_A_HI 0
#define GU_A_LO 18432
#define GU_BG_HI 36864
#define GU_BG_LO 46080
#define GU_BU_HI 55296
#define GU_BU_LO 64512
#define GU_STAGE 73728
#define GU_SMEM (1024 + 2 * GU_STAGE)   // 148480

__global__ void __launch_bounds__(256)
gu_mma(const float* __restrict__ x,
       const float* __restrict__ Wg, const float* __restrict__ Wu,
       const float* __restrict__ wsg, const float* __restrict__ wsu) {
    extern __shared__ char smem[];
    int tid = threadIdx.x;
    int z = blockIdx.z;
    bool SH = (z == E_EXP);
    int ne = SH ? T_TOK : g_cnt[z];
    int m0 = blockIdx.y * 128;
    if (m0 >= ne) return;
    int n0 = blockIdx.x * 64;
    const float* wgp = SH ? wsg : (Wg + (size_t)z * F_DIM * D_DIM);
    const float* wup = SH ? wsu : (Wu + (size_t)z * F_DIM * D_DIM);

    int* s_pair = (int*)smem;
    int* s_src  = (int*)(smem + 512);
    if (tid < 128) {
        int m = m0 + tid;
        int pair = SH ? m : ((m < ne) ? g_pairs[z * T_TOK + m] : g_pairs[z * T_TOK]);
        s_pair[tid] = pair;
        s_src[tid]  = SH ? m : (pair >> 2);
    }
    __syncthreads();

    const int c4 = tid & 15;         // float4 column within K-chunk
    const int rb = tid >> 4;         // base row (0..15)

    // global row pointers
    const float* aptr[8];
#pragma unroll
    for (int j = 0; j < 8; ++j)
        aptr[j] = x + (size_t)s_src[rb + 16 * j] * D_DIM + c4 * 4;
    const float* gptr[4];
    const float* uptr[4];
#pragma unroll
    for (int j = 0; j < 4; ++j) {
        gptr[j] = wgp + (size_t)(n0 + rb + 16 * j) * D_DIM + c4 * 4;
        uptr[j] = wup + (size_t)(n0 + rb + 16 * j) * D_DIM + c4 * 4;
    }

    const int wid = tid >> 5, lane = tid & 31;
    const bool isUp = wid >= 4;
    const int q = wid & 3;
    const int wm = q >> 1, wn = q & 1;  // warp: rows wm*64, cols wn*32

    float acc[4][4][4] = {};

    float4 ra[8], rg[4], ru[4];
#pragma unroll
    for (int j = 0; j < 8; ++j) ra[j] = *(const float4*)(aptr[j]);
#pragma unroll
    for (int j = 0; j < 4; ++j) { rg[j] = *(const float4*)(gptr[j]); ru[j] = *(const float4*)(uptr[j]); }

    // fragment address components
    const uint32_t a_row = wm * 64 + (lane & 15);
    const uint32_t a_colb = (lane >> 4) * 16;
    const uint32_t b_row = wn * 32 + ((lane >> 3) >> 1) * 8 + (lane & 7);
    const uint32_t b_colb = ((lane >> 3) & 1) * 16;

#define GU_STORE(BUF) do { \
    char* p; \
    _Pragma("unroll") \
    for (int j = 0; j < 8; ++j) { \
        p = (BUF) + (rb + 16 * j) * APITCH + c4 * 8; \
        split_store4(p + GU_A_HI, p + GU_A_LO, ra[j]); \
    } \
    _Pragma("unroll") \
    for (int j = 0; j < 4; ++j) { \
        p = (BUF) + (rb + 16 * j) * APITCH + c4 * 8; \
        split_store4(p + GU_BG_HI, p + GU_BG_LO, rg[j]); \
        split_store4(p + GU_BU_HI, p + GU_BU_LO, ru[j]); \
    } \
} while (0)

    GU_STORE(smem + 1024);
    __syncthreads();

    for (int ch = 0; ch < 16; ++ch) {
        if (ch < 15) {
            int k0 = (ch + 1) * 64;
#pragma unroll
            for (int j = 0; j < 8; ++j) ra[j] = *(const float4*)(aptr[j] + k0);
#pragma unroll
            for (int j = 0; j < 4; ++j) { rg[j] = *(const float4*)(gptr[j] + k0); ru[j] = *(const float4*)(uptr[j] + k0); }
        }
        {
            char* cur = smem + 1024 + (ch & 1) * GU_STAGE;
            uint32_t abase = smem_u32(cur) + GU_A_HI;
            uint32_t bbase = smem_u32(cur) + (isUp ? GU_BU_HI : GU_BG_HI);
#pragma unroll
            for (int ks = 0; ks < 4; ++ks) {
                uint32_t koff = ks * 32;
                uint32_t ah[4][4], al[4][4];
#pragma unroll
                for (int mt = 0; mt < 4; ++mt) {
                    uint32_t ad = abase + (a_row + mt * 16) * APITCH + koff + a_colb;
                    ldm4(ah[mt], ad);
                    ldm4(al[mt], ad + GU_A_LO);
                }
                uint32_t bh[8], bl[8];
#pragma unroll
                for (int p = 0; p < 2; ++p) {
                    uint32_t bd = bbase + (b_row + p * 16) * APITCH + koff + b_colb;
                    ldm4(&bh[p * 4], bd);
                    ldm4(&bl[p * 4], bd + GU_BG_LO - GU_BG_HI);
                }
#pragma unroll
                for (int mt = 0; mt < 4; ++mt)
#pragma unroll
                    for (int nt = 0; nt < 4; ++nt) {
                        float* d = acc[mt][nt];
                        mma16816(d, ah[mt], &bh[nt * 2]);
                        mma16816(d, ah[mt], &bl[nt * 2]);
                        mma16816(d, al[mt], &bh[nt * 2]);
                    }
            }
        }
        if (ch < 15) {
            char* nxt = smem + 1024 + ((ch + 1) & 1) * GU_STAGE;
            GU_STORE(nxt);
            __syncthreads();
        }
    }
    __syncthreads();

    // epilogue: stage gate + up fp32 tiles, compute silu(g)*u, pack, store
    float* stg_g = (float*)(smem + 1024);
    float* stg_u = stg_g + 128 * 66;
    float* mystg = isUp ? stg_u : stg_g;
#pragma unroll
    for (int mt = 0; mt < 4; ++mt)
#pragma unroll
        for (int nt = 0; nt < 4; ++nt) {
            int r = wm * 64 + mt * 16 + (lane >> 2);
            int c = wn * 32 + nt * 8 + (lane & 3) * 2;
            *(float2*)&mystg[r * 66 + c]       = make_float2(acc[mt][nt][0], acc[mt][nt][1]);
            *(float2*)&mystg[(r + 8) * 66 + c] = make_float2(acc[mt][nt][2], acc[mt][nt][3]);
        }
    __syncthreads();

    uint32_t* dst = SH ? g_hsp : g_hp;
#pragma unroll
    for (int pass = 0; pass < 2; ++pass) {
        int r = (tid >> 2) + 64 * pass;
        int c0 = (tid & 3) * 16;
        uint32_t* drow = dst + (size_t)s_pair[r] * F_DIM + n0 + c0;
#pragma unroll
        for (int jj = 0; jj < 16; jj += 4) {
            uint4 o;
            uint32_t* po = &o.x;
#pragma unroll
            for (int k = 0; k < 4; ++k) {
                float gg = stg_g[r * 66 + c0 + jj + k];
                float uu = stg_u[r * 66 + c0 + jj + k];
                float h = gg / (1.f + __expf(-gg)) * uu;
                po[k] = pack_split1(h);
            }
            *(uint4*)(drow + jj) = o;
        }
    }
}

// ================= down warp-MMA kernel =================
// CTA: 128(M pairs) x 64(N of D). BK=64 over F. 8 warps 32x32 (MT=2, NT=4).
#define DN_A_HI 0
#define DN_A_LO 18432
#define DN_B_HI 36864
#define DN_B_LO 46080
#define DN_STAGE 55296
#define DN_SMEM (1024 + 2 * DN_STAGE)   // 111616

template <bool SH>
__global__ void __launch_bounds__(256)
dn_mma(const float* __restrict__ Wd, float* __restrict__ out) {
    extern __shared__ char smem[];
    int tid = threadIdx.x;
    int z = SH ? 0 : blockIdx.z;
    int ne = SH ? T_TOK : g_cnt[z];
    int m0 = blockIdx.y * 128;
    if (m0 >= ne) return;
    int n0 = blockIdx.x * 64;
    const float* wdp = SH ? Wd : (Wd + (size_t)z * D_DIM * F_DIM);
    const uint32_t* hsrc = SH ? g_hsp : g_hp;

    int* s_pair = (int*)smem;
    if (tid < 128) {
        int m = m0 + tid;
        s_pair[tid] = SH ? m : ((m < ne) ? g_pairs[z * T_TOK + m] : g_pairs[z * T_TOK]);
    }
    __syncthreads();

    const int c4 = tid & 15;
    const int rb = tid >> 4;

    const uint32_t* aptr[8];
#pragma unroll
    for (int j = 0; j < 8; ++j)
        aptr[j] = hsrc + (size_t)s_pair[rb + 16 * j] * F_DIM + c4 * 4;
    const float* bptr[4];
#pragma unroll
    for (int j = 0; j < 4; ++j)
        bptr[j] = wdp + (size_t)(n0 + rb + 16 * j) * F_DIM + c4 * 4;

    const int wid = tid >> 5, lane = tid & 31;
    const int wm = wid >> 1, wn = wid & 1;  // rows wm*32, cols wn*32

    float acc[2][4][4] = {};

    uint4  rha[8];
    float4 rwb[4];
#pragma unroll
    for (int j = 0; j < 8; ++j) rha[j] = *(const uint4*)(aptr[j]);
#pragma unroll
    for (int j = 0; j < 4; ++j) rwb[j] = *(const float4*)(bptr[j]);

    const uint32_t a_row = wm * 32 + (lane & 15);
    const uint32_t a_colb = (lane >> 4) * 16;
    const uint32_t b_row = wn * 32 + ((lane >> 3) >> 1) * 8 + (lane & 7);
    const uint32_t b_colb = ((lane >> 3) & 1) * 16;

#define DN_STORE(BUF) do { \
    char* p; \
    _Pragma("unroll") \
    for (int j = 0; j < 8; ++j) { \
        p = (BUF) + (rb + 16 * j) * APITCH + c4 * 8; \
        uint32_t h0 = __byte_perm(rha[j].x, rha[j].y, 0x5410); \
        uint32_t h1 = __byte_perm(rha[j].z, rha[j].w, 0x5410); \
        uint32_t l0 = __byte_perm(rha[j].x, rha[j].y, 0x7632); \
        uint32_t l1 = __byte_perm(rha[j].z, rha[j].w, 0x7632); \
        *(uint2*)(p + DN_A_HI) = make_uint2(h0, h1); \
        *(uint2*)(p + DN_A_LO) = make_uint2(l0, l1); \
    } \
    _Pragma("unroll") \
    for (int j = 0; j < 4; ++j) { \
        p = (BUF) + (rb + 16 * j) * APITCH + c4 * 8; \
        split_store4(p + DN_B_HI, p + DN_B_LO, rwb[j]); \
    } \
} while (0)

    DN_STORE(smem + 1024);
    __syncthreads();

    for (int ch = 0; ch < 32; ++ch) {
        if (ch < 31) {
            int k0 = (ch + 1) * 64;
#pragma unroll
            for (int j = 0; j < 8; ++j) rha[j] = *(const uint4*)(aptr[j] + k0);
#pragma unroll
            for (int j = 0; j < 4; ++j) rwb[j] = *(const float4*)(bptr[j] + k0);
        }
        {
            char* cur = smem + 1024 + (ch & 1) * DN_STAGE;
            uint32_t abase = smem_u32(cur) + DN_A_HI;
            uint32_t bbase = smem_u32(cur) + DN_B_HI;
#pragma unroll
            for (int ks = 0; ks < 4; ++ks) {
                uint32_t koff = ks * 32;
                uint32_t ah[2][4], al[2][4];
#pragma unroll
                for (int mt = 0; mt < 2; ++mt) {
                    uint32_t ad = abase + (a_row + mt * 16) * APITCH + koff + a_colb;
                    ldm4(ah[mt], ad);
                    ldm4(al[mt], ad + DN_A_LO);
                }
                uint32_t bh[8], bl[8];
#pragma unroll
                for (int p = 0; p < 2; ++p) {
                    uint32_t bd = bbase + (b_row + p * 16) * APITCH + koff + b_colb;
                    ldm4(&bh[p * 4], bd);
                    ldm4(&bl[p * 4], bd + DN_B_LO - DN_B_HI);
                }
#pragma unroll
                for (int mt = 0; mt < 2; ++mt)
#pragma unroll
                    for (int nt = 0; nt < 4; ++nt) {
                        float* d = acc[mt][nt];
                        mma16816(d, ah[mt], &bh[nt * 2]);
                        mma16816(d, ah[mt], &bl[nt * 2]);
                        mma16816(d, al[mt], &bh[nt * 2]);
                    }
            }
        }
        if (ch < 31) {
            char* nxt = smem + 1024 + ((ch + 1) & 1) * DN_STAGE;
            DN_STORE(nxt);
            __syncthreads();
        }
    }
    __syncthreads();

    float* stg = (float*)(smem + 1024);
#pragma unroll
    for (int mt = 0; mt < 2; ++mt)
#pragma unroll
        for (int nt = 0; nt < 4; ++nt) {
            int r = wm * 32 + mt * 16 + (lane >> 2);
            int c = wn * 32 + nt * 8 + (lane & 3) * 2;
            *(float2*)&stg[r * 66 + c]       = make_float2(acc[mt][nt][0], acc[mt][nt][1]);
            *(float2*)&stg[(r + 8) * 66 + c] = make_float2(acc[mt][nt][2], acc[mt][nt][3]);
        }
    __syncthreads();

    {
        int r = tid >> 1;
        int c0 = (tid & 1) * 32;
        float* drow;
        if (SH) drow = out + (size_t)(m0 + r) * D_DIM + n0 + c0;
        else    drow = g_y + (size_t)s_pair[r] * D_DIM + n0 + c0;
#pragma unroll
        for (int jj = 0; jj < 32; jj += 4) {
            float4 v = make_float4(stg[r * 66 + c0 + jj], stg[r * 66 + c0 + jj + 1],
                                   stg[r * 66 + c0 + jj + 2], stg[r * 66 + c0 + jj + 3]);
            *(float4*)(drow + jj) = v;
        }
    }
}

// ================= combine: out += sum_k w_k * y_pair =================
__global__ void combine_kernel(float* __restrict__ out) {
    int t = blockIdx.x;
    int c = threadIdx.x * 4;
    float4 o = *(float4*)(out + (size_t)t * D_DIM + c);
#pragma unroll
    for (int k = 0; k < TOPK; ++k) {
        int pair = t * TOPK + k;
        float w = g_w[pair];
        float4 y = *(const float4*)(g_y + (size_t)pair * D_DIM + c);
        o.x += w * y.x; o.y += w * y.y; o.z += w * y.z; o.w += w * y.w;
    }
    *(float4*)(out + (size_t)t * D_DIM + c) = o;
}

// ---------------- launch ----------------
extern "C" void kernel_launch(void* const* d_in, const int* in_sizes, int n_in,
                              void* d_out, int out_size) {
    const float* x    = (const float*)d_in[0];
    const float* gw   = (const float*)d_in[1];
    const float* bias = (const float*)d_in[2];
    const float* wg   = (const float*)d_in[3];
    const float* wu   = (const float*)d_in[4];
    const float* wd   = (const float*)d_in[5];
    const float* wsg  = (const float*)d_in[6];
    const float* wsu  = (const float*)d_in[7];
    const float* wsd  = (const float*)d_in[8];
    float* out = (float*)d_out;

    static int attr_done = 0;
    if (!attr_done) {
        cudaFuncSetAttribute(gu_mma, cudaFuncAttributeMaxDynamicSharedMemorySize, GU_SMEM);
        cudaFuncSetAttribute(dn_mma<true>,  cudaFuncAttributeMaxDynamicSharedMemorySize, DN_SMEM);
        cudaFuncSetAttribute(dn_mma<false>, cudaFuncAttributeMaxDynamicSharedMemorySize, DN_SMEM);
        attr_done = 1;
    }

    zero_kernel<<<1, 32>>>();
    router_kernel<<<T_TOK, 128>>>(x, gw, bias);

    float* tail = (out_size >= T_TOK * D_DIM + E_EXP + 1) ? (out + T_TOK * D_DIM) : nullptr;
    stats_kernel<<<1, 32>>>(tail);

    // gate+up: routed z=0..31, shared z=32
    gu_mma<<<dim3(F_DIM / 64, T_TOK / 128, E_EXP + 1), 256, GU_SMEM>>>(x, wg, wu, wsg, wsu);

    // shared down: writes all of out
    dn_mma<true><<<dim3(D_DIM / 64, T_TOK / 128), 256, DN_SMEM>>>(wsd, out);

    // routed down: per-pair rows into g_y
    dn_mma<false><<<dim3(D_DIM / 64, T_TOK / 128, E_EXP), 256, DN_SMEM>>>(wd, out);

    // weighted combine
    combine_kernel<<<T_TOK, 256>>>(out);
}

// round 4
// speedup vs baseline: 2.7493x; 1.0361x over previous
#include <cuda_runtime.h>
#include <cuda_bf16.h>
#include <stdint.h>

#define T_TOK 1024
#define D_DIM 1024
#define F_DIM 2048
#define E_EXP 32
#define TOPK  4
#define NPAIR (T_TOK * TOPK)

// ---------------- static scratch ----------------
__device__ int      g_cnt[E_EXP];
__device__ int      g_pairs[E_EXP * T_TOK];
__device__ float    g_w[NPAIR];
__device__ uint32_t g_hp[(size_t)NPAIR * F_DIM];   // routed hidden packed bf16 hi|lo<<16
__device__ uint32_t g_hsp[(size_t)T_TOK * F_DIM];  // shared hidden packed
__device__ float    g_y[(size_t)NPAIR * D_DIM];    // routed per-pair down output

// ---------------- helpers ----------------
__device__ __forceinline__ uint32_t smem_u32(const void* p) {
    uint32_t a;
    asm("{ .reg .u64 t; cvta.to.shared.u64 t, %1; cvt.u32.u64 %0, t; }" : "=r"(a) : "l"(p));
    return a;
}
__device__ __forceinline__ void ldm4(uint32_t* r, uint32_t addr) {
    asm volatile("ldmatrix.sync.aligned.m8n8.x4.shared.b16 {%0,%1,%2,%3}, [%4];"
                 : "=r"(r[0]), "=r"(r[1]), "=r"(r[2]), "=r"(r[3]) : "r"(addr));
}
__device__ __forceinline__ void mma16816(float* d, const uint32_t* a, const uint32_t* b) {
    asm volatile("mma.sync.aligned.m16n8k16.row.col.f32.bf16.bf16.f32 "
                 "{%0,%1,%2,%3}, {%4,%5,%6,%7}, {%8,%9}, {%0,%1,%2,%3};"
                 : "+f"(d[0]), "+f"(d[1]), "+f"(d[2]), "+f"(d[3])
                 : "r"(a[0]), "r"(a[1]), "r"(a[2]), "r"(a[3]), "r"(b[0]), "r"(b[1]));
}
__device__ __forceinline__ void cvt_split(float x0, float x1, uint32_t& hi, uint32_t& lo) {
    asm("cvt.rn.bf16x2.f32 %0, %1, %2;" : "=r"(hi) : "f"(x1), "f"(x0));
    float f0 = __uint_as_float(hi << 16);
    float f1 = __uint_as_float(hi & 0xffff0000u);
    float r0 = x0 - f0, r1 = x1 - f1;
    asm("cvt.rn.bf16x2.f32 %0, %1, %2;" : "=r"(lo) : "f"(r1), "f"(r0));
}
__device__ __forceinline__ void split_store4(char* hi, char* lo, float4 v) {
    uint32_t h0, l0, h1, l1;
    cvt_split(v.x, v.y, h0, l0);
    cvt_split(v.z, v.w, h1, l1);
    *(uint2*)hi = make_uint2(h0, h1);
    *(uint2*)lo = make_uint2(l0, l1);
}
__device__ __forceinline__ uint32_t pack_split1(float h) {
    __nv_bfloat16 hb = __float2bfloat16_rn(h);
    float r = h - __bfloat162float(hb);
    __nv_bfloat16 lb = __float2bfloat16_rn(r);
    return (uint32_t)__bfloat16_as_ushort(hb) | ((uint32_t)__bfloat16_as_ushort(lb) << 16);
}

// ---------------- tiny kernels ----------------
__global__ void zero_kernel() {
    if (threadIdx.x < E_EXP) g_cnt[threadIdx.x] = 0;
}

__global__ void router_kernel(const float* __restrict__ x,
                              const float* __restrict__ gw,
                              const float* __restrict__ bias) {
    __shared__ float xs[D_DIM];
    __shared__ float logits[E_EXP];
    int t = blockIdx.x;
    const float4* xr = (const float4*)(x + (size_t)t * D_DIM);
    for (int i = threadIdx.x; i < D_DIM / 4; i += blockDim.x)
        ((float4*)xs)[i] = xr[i];
    __syncthreads();

    int e = threadIdx.x >> 2;
    int g = threadIdx.x & 3;
    const float4* wrow = (const float4*)(gw + (size_t)e * D_DIM);
    float s = 0.f;
    for (int d4 = g; d4 < D_DIM / 4; d4 += 4) {
        float4 a = ((const float4*)xs)[d4];
        float4 b = wrow[d4];
        s += a.x * b.x + a.y * b.y + a.z * b.z + a.w * b.w;
    }
    s += __shfl_down_sync(0xffffffffu, s, 2, 4);
    s += __shfl_down_sync(0xffffffffu, s, 1, 4);
    if (g == 0) logits[e] = s + bias[e];
    __syncthreads();

    if (threadIdx.x == 0) {
        float v[TOPK]; int idx[TOPK];
        unsigned used = 0;
        for (int k = 0; k < TOPK; k++) {
            float best = -3.4e38f; int bi = 0;
            for (int j = 0; j < E_EXP; j++) {
                if (used & (1u << j)) continue;
                if (logits[j] > best) { best = logits[j]; bi = j; }
            }
            used |= 1u << bi; v[k] = best; idx[k] = bi;
        }
        float ex[TOPK], sum = 0.f;
        for (int k = 0; k < TOPK; k++) { ex[k] = __expf(v[k] - v[0]); sum += ex[k]; }
        float inv = 1.f / sum;
        for (int k = 0; k < TOPK; k++) {
            int ek = idx[k];
            int slot = atomicAdd(&g_cnt[ek], 1);
            g_pairs[ek * T_TOK + slot] = t * TOPK + k;
            g_w[t * TOPK + k] = ex[k] * inv;
        }
    }
}

__global__ void stats_kernel(float* __restrict__ tail) {
    int e = threadIdx.x;
    float c = (float)g_cnt[e];
    float mean = (float)(T_TOK * TOPK) / E_EXP;
    float d = c - mean;
    float v = d * d;
    for (int o = 16; o > 0; o >>= 1) v += __shfl_down_sync(0xffffffffu, v, o);
    if (tail) {
        tail[e] = c;
        if (e == 0) tail[E_EXP] = sqrtf(v / E_EXP) / (mean + 1e-6f);
    }
}

// ================= gate+up warp-MMA kernel =================
// CTA 128M x 64N(F), 512 threads, 16 warps of 32x32 (8 gate, 8 up). BK=64.
#define APITCH 144
#define GU_A_HI 0
#define GU_A_LO 18432
#define GU_BG_HI 36864
#define GU_BG_LO 46080
#define GU_BU_HI 55296
#define GU_BU_LO 64512
#define GU_STAGE 73728
#define GU_SMEM (1024 + 2 * GU_STAGE)   // 148480

__global__ void __launch_bounds__(512, 1)
gu_mma(const float* __restrict__ x,
       const float* __restrict__ Wg, const float* __restrict__ Wu,
       const float* __restrict__ wsg, const float* __restrict__ wsu) {
    extern __shared__ char smem[];
    int tid = threadIdx.x;
    int z = blockIdx.z;
    bool SH = (z == E_EXP);
    int ne = SH ? T_TOK : g_cnt[z];
    int m0 = blockIdx.y * 128;
    if (m0 >= ne) return;
    int n0 = blockIdx.x * 64;
    const float* wgp = SH ? wsg : (Wg + (size_t)z * F_DIM * D_DIM);
    const float* wup = SH ? wsu : (Wu + (size_t)z * F_DIM * D_DIM);

    int* s_pair = (int*)smem;
    int* s_src  = (int*)(smem + 512);
    if (tid < 128) {
        int m = m0 + tid;
        int pair = SH ? m : ((m < ne) ? g_pairs[z * T_TOK + m] : g_pairs[z * T_TOK]);
        s_pair[tid] = pair;
        s_src[tid]  = SH ? m : (pair >> 2);
    }
    __syncthreads();

    const int c4 = tid & 15;       // float4 column within K-chunk
    const int rb = tid >> 4;       // base row (0..31)

    const float* aptr[4];
#pragma unroll
    for (int j = 0; j < 4; ++j)
        aptr[j] = x + (size_t)s_src[rb + 32 * j] * D_DIM + c4 * 4;
    const float* gptr[2];
    const float* uptr[2];
#pragma unroll
    for (int j = 0; j < 2; ++j) {
        gptr[j] = wgp + (size_t)(n0 + rb + 32 * j) * D_DIM + c4 * 4;
        uptr[j] = wup + (size_t)(n0 + rb + 32 * j) * D_DIM + c4 * 4;
    }

    const int wid = tid >> 5, lane = tid & 31;
    const bool isUp = wid >= 8;
    const int q = wid & 7;
    const int wm = q >> 1, wn = q & 1;   // warp: rows wm*32, cols wn*32

    float acc[2][4][4] = {};

    float4 ra[4], rg[2], ru[2];
#pragma unroll
    for (int j = 0; j < 4; ++j) ra[j] = *(const float4*)(aptr[j]);
#pragma unroll
    for (int j = 0; j < 2; ++j) { rg[j] = *(const float4*)(gptr[j]); ru[j] = *(const float4*)(uptr[j]); }

    const uint32_t a_row = wm * 32 + (lane & 15);
    const uint32_t a_colb = (lane >> 4) * 16;
    const uint32_t b_row = wn * 32 + ((lane >> 3) >> 1) * 8 + (lane & 7);
    const uint32_t b_colb = ((lane >> 3) & 1) * 16;

#define GU_STORE(BUF) do { \
    char* p; \
    _Pragma("unroll") \
    for (int j = 0; j < 4; ++j) { \
        p = (BUF) + (rb + 32 * j) * APITCH + c4 * 8; \
        split_store4(p + GU_A_HI, p + GU_A_LO, ra[j]); \
    } \
    _Pragma("unroll") \
    for (int j = 0; j < 2; ++j) { \
        p = (BUF) + (rb + 32 * j) * APITCH + c4 * 8; \
        split_store4(p + GU_BG_HI, p + GU_BG_LO, rg[j]); \
        split_store4(p + GU_BU_HI, p + GU_BU_LO, ru[j]); \
    } \
} while (0)

    GU_STORE(smem + 1024);
    __syncthreads();

    for (int ch = 0; ch < 16; ++ch) {
        if (ch < 15) {
            int k0 = (ch + 1) * 64;
#pragma unroll
            for (int j = 0; j < 4; ++j) ra[j] = *(const float4*)(aptr[j] + k0);
#pragma unroll
            for (int j = 0; j < 2; ++j) { rg[j] = *(const float4*)(gptr[j] + k0); ru[j] = *(const float4*)(uptr[j] + k0); }
        }
        {
            char* cur = smem + 1024 + (ch & 1) * GU_STAGE;
            uint32_t abase = smem_u32(cur) + GU_A_HI;
            uint32_t bbase = smem_u32(cur) + (isUp ? GU_BU_HI : GU_BG_HI);
#pragma unroll
            for (int ks = 0; ks < 4; ++ks) {
                uint32_t koff = ks * 32;
                uint32_t ah[2][4], al[2][4];
#pragma unroll
                for (int mt = 0; mt < 2; ++mt) {
                    uint32_t ad = abase + (a_row + mt * 16) * APITCH + koff + a_colb;
                    ldm4(ah[mt], ad);
                    ldm4(al[mt], ad + GU_A_LO);
                }
                uint32_t bh[8], bl[8];
#pragma unroll
                for (int p = 0; p < 2; ++p) {
                    uint32_t bd = bbase + (b_row + p * 16) * APITCH + koff + b_colb;
                    ldm4(&bh[p * 4], bd);
                    ldm4(&bl[p * 4], bd + GU_BG_LO - GU_BG_HI);
                }
#pragma unroll
                for (int mt = 0; mt < 2; ++mt)
#pragma unroll
                    for (int nt = 0; nt < 4; ++nt) {
                        float* d = acc[mt][nt];
                        mma16816(d, ah[mt], &bh[nt * 2]);
                        mma16816(d, ah[mt], &bl[nt * 2]);
                        mma16816(d, al[mt], &bh[nt * 2]);
                    }
            }
        }
        if (ch < 15) {
            char* nxt = smem + 1024 + ((ch + 1) & 1) * GU_STAGE;
            GU_STORE(nxt);
            __syncthreads();
        }
    }
    __syncthreads();

    // epilogue: stage gate+up fp32, silu, pack, store
    float* stg_g = (float*)(smem + 1024);
    float* stg_u = stg_g + 128 * 66;
    float* mystg = isUp ? stg_u : stg_g;
#pragma unroll
    for (int mt = 0; mt < 2; ++mt)
#pragma unroll
        for (int nt = 0; nt < 4; ++nt) {
            int r = wm * 32 + mt * 16 + (lane >> 2);
            int c = wn * 32 + nt * 8 + (lane & 3) * 2;
            *(float2*)&mystg[r * 66 + c]       = make_float2(acc[mt][nt][0], acc[mt][nt][1]);
            *(float2*)&mystg[(r + 8) * 66 + c] = make_float2(acc[mt][nt][2], acc[mt][nt][3]);
        }
    __syncthreads();

    uint32_t* dst = SH ? g_hsp : g_hp;
    {
        int r = tid >> 2;
        int c0 = (tid & 3) * 16;
        uint32_t* drow = dst + (size_t)s_pair[r] * F_DIM + n0 + c0;
#pragma unroll
        for (int jj = 0; jj < 16; jj += 4) {
            uint4 o;
            uint32_t* po = &o.x;
#pragma unroll
            for (int k = 0; k < 4; ++k) {
                float gg = stg_g[r * 66 + c0 + jj + k];
                float uu = stg_u[r * 66 + c0 + jj + k];
                float h = gg / (1.f + __expf(-gg)) * uu;
                po[k] = pack_split1(h);
            }
            *(uint4*)(drow + jj) = o;
        }
    }
}

// ================= down warp-MMA kernel =================
// CTA 128M x 128N(D), 512 threads, 16 warps of 32x32 (4x4). BK=64 over F.
#define DN_A_HI 0
#define DN_A_LO 18432
#define DN_B_HI 36864
#define DN_B_LO 55296
#define DN_STAGE 73728
#define DN_SMEM (1024 + 2 * DN_STAGE)   // 148480

template <bool SH>
__global__ void __launch_bounds__(512, 1)
dn_mma(const float* __restrict__ Wd, float* __restrict__ out) {
    extern __shared__ char smem[];
    int tid = threadIdx.x;
    int z = SH ? 0 : blockIdx.z;
    int ne = SH ? T_TOK : g_cnt[z];
    int m0 = blockIdx.y * 128;
    if (m0 >= ne) return;
    int n0 = blockIdx.x * 128;
    const float* wdp = SH ? Wd : (Wd + (size_t)z * D_DIM * F_DIM);
    const uint32_t* hsrc = SH ? g_hsp : g_hp;

    int* s_pair = (int*)smem;
    if (tid < 128) {
        int m = m0 + tid;
        s_pair[tid] = SH ? m : ((m < ne) ? g_pairs[z * T_TOK + m] : g_pairs[z * T_TOK]);
    }
    __syncthreads();

    const int c4 = tid & 15;
    const int rb = tid >> 4;

    const uint32_t* aptr[4];
#pragma unroll
    for (int j = 0; j < 4; ++j)
        aptr[j] = hsrc + (size_t)s_pair[rb + 32 * j] * F_DIM + c4 * 4;
    const float* bptr[4];
#pragma unroll
    for (int j = 0; j < 4; ++j)
        bptr[j] = wdp + (size_t)(n0 + rb + 32 * j) * F_DIM + c4 * 4;

    const int wid = tid >> 5, lane = tid & 31;
    const int wm = wid >> 2, wn = wid & 3;   // rows wm*32, cols wn*32

    float acc[2][4][4] = {};

    uint4  rha[4];
    float4 rwb[4];
#pragma unroll
    for (int j = 0; j < 4; ++j) rha[j] = *(const uint4*)(aptr[j]);
#pragma unroll
    for (int j = 0; j < 4; ++j) rwb[j] = *(const float4*)(bptr[j]);

    const uint32_t a_row = wm * 32 + (lane & 15);
    const uint32_t a_colb = (lane >> 4) * 16;
    const uint32_t b_row = wn * 32 + ((lane >> 3) >> 1) * 8 + (lane & 7);
    const uint32_t b_colb = ((lane >> 3) & 1) * 16;

#define DN_STORE(BUF) do { \
    char* p; \
    _Pragma("unroll") \
    for (int j = 0; j < 4; ++j) { \
        p = (BUF) + (rb + 32 * j) * APITCH + c4 * 8; \
        uint32_t h0 = __byte_perm(rha[j].x, rha[j].y, 0x5410); \
        uint32_t h1 = __byte_perm(rha[j].z, rha[j].w, 0x5410); \
        uint32_t l0 = __byte_perm(rha[j].x, rha[j].y, 0x7632); \
        uint32_t l1 = __byte_perm(rha[j].z, rha[j].w, 0x7632); \
        *(uint2*)(p + DN_A_HI) = make_uint2(h0, h1); \
        *(uint2*)(p + DN_A_LO) = make_uint2(l0, l1); \
    } \
    _Pragma("unroll") \
    for (int j = 0; j < 4; ++j) { \
        p = (BUF) + (rb + 32 * j) * APITCH + c4 * 8; \
        split_store4(p + DN_B_HI, p + DN_B_LO, rwb[j]); \
    } \
} while (0)

    DN_STORE(smem + 1024);
    __syncthreads();

    for (int ch = 0; ch < 32; ++ch) {
        if (ch < 31) {
            int k0 = (ch + 1) * 64;
#pragma unroll
            for (int j = 0; j < 4; ++j) rha[j] = *(const uint4*)(aptr[j] + k0);
#pragma unroll
            for (int j = 0; j < 4; ++j) rwb[j] = *(const float4*)(bptr[j] + k0);
        }
        {
            char* cur = smem + 1024 + (ch & 1) * DN_STAGE;
            uint32_t abase = smem_u32(cur) + DN_A_HI;
            uint32_t bbase = smem_u32(cur) + DN_B_HI;
#pragma unroll
            for (int ks = 0; ks < 4; ++ks) {
                uint32_t koff = ks * 32;
                uint32_t ah[2][4], al[2][4];
#pragma unroll
                for (int mt = 0; mt < 2; ++mt) {
                    uint32_t ad = abase + (a_row + mt * 16) * APITCH + koff + a_colb;
                    ldm4(ah[mt], ad);
                    ldm4(al[mt], ad + DN_A_LO);
                }
                uint32_t bh[8], bl[8];
#pragma unroll
                for (int p = 0; p < 2; ++p) {
                    uint32_t bd = bbase + (b_row + p * 16) * APITCH + koff + b_colb;
                    ldm4(&bh[p * 4], bd);
                    ldm4(&bl[p * 4], bd + DN_B_LO - DN_B_HI);
                }
#pragma unroll
                for (int mt = 0; mt < 2; ++mt)
#pragma unroll
                    for (int nt = 0; nt < 4; ++nt) {
                        float* d = acc[mt][nt];
                        mma16816(d, ah[mt], &bh[nt * 2]);
                        mma16816(d, ah[mt], &bl[nt * 2]);
                        mma16816(d, al[mt], &bh[nt * 2]);
                    }
            }
        }
        if (ch < 31) {
            char* nxt = smem + 1024 + ((ch + 1) & 1) * DN_STAGE;
            DN_STORE(nxt);
            __syncthreads();
        }
    }
    __syncthreads();

    float* stg = (float*)(smem + 1024);
#pragma unroll
    for (int mt = 0; mt < 2; ++mt)
#pragma unroll
        for (int nt = 0; nt < 4; ++nt) {
            int r = wm * 32 + mt * 16 + (lane >> 2);
            int c = wn * 32 + nt * 8 + (lane & 3) * 2;
            *(float2*)&stg[r * 132 + c]       = make_float2(acc[mt][nt][0], acc[mt][nt][1]);
            *(float2*)&stg[(r + 8) * 132 + c] = make_float2(acc[mt][nt][2], acc[mt][nt][3]);
        }
    __syncthreads();

    {
        int r = tid >> 2;
        int c0 = (tid & 3) * 32;
        float* drow;
        if (SH) drow = out + (size_t)(m0 + r) * D_DIM + n0 + c0;
        else    drow = g_y + (size_t)s_pair[r] * D_DIM + n0 + c0;
#pragma unroll
        for (int jj = 0; jj < 32; jj += 4) {
            float4 v = make_float4(stg[r * 132 + c0 + jj], stg[r * 132 + c0 + jj + 1],
                                   stg[r * 132 + c0 + jj + 2], stg[r * 132 + c0 + jj + 3]);
            *(float4*)(drow + jj) = v;
        }
    }
}

// ================= combine: out += sum_k w_k * y_pair =================
__global__ void combine_kernel(float* __restrict__ out) {
    int t = blockIdx.x;
    int c = threadIdx.x * 4;
    float4 o = *(float4*)(out + (size_t)t * D_DIM + c);
#pragma unroll
    for (int k = 0; k < TOPK; ++k) {
        int pair = t * TOPK + k;
        float w = g_w[pair];
        float4 y = *(const float4*)(g_y + (size_t)pair * D_DIM + c);
        o.x += w * y.x; o.y += w * y.y; o.z += w * y.z; o.w += w * y.w;
    }
    *(float4*)(out + (size_t)t * D_DIM + c) = o;
}

// ---------------- launch ----------------
extern "C" void kernel_launch(void* const* d_in, const int* in_sizes, int n_in,
                              void* d_out, int out_size) {
    const float* x    = (const float*)d_in[0];
    const float* gw   = (const float*)d_in[1];
    const float* bias = (const float*)d_in[2];
    const float* wg   = (const float*)d_in[3];
    const float* wu   = (const float*)d_in[4];
    const float* wd   = (const float*)d_in[5];
    const float* wsg  = (const float*)d_in[6];
    const float* wsu  = (const float*)d_in[7];
    const float* wsd  = (const float*)d_in[8];
    float* out = (float*)d_out;

    static int attr_done = 0;
    if (!attr_done) {
        cudaFuncSetAttribute(gu_mma, cudaFuncAttributeMaxDynamicSharedMemorySize, GU_SMEM);
        cudaFuncSetAttribute(dn_mma<true>,  cudaFuncAttributeMaxDynamicSharedMemorySize, DN_SMEM);
        cudaFuncSetAttribute(dn_mma<false>, cudaFuncAttributeMaxDynamicSharedMemorySize, DN_SMEM);
        attr_done = 1;
    }

    zero_kernel<<<1, 32>>>();
    router_kernel<<<T_TOK, 128>>>(x, gw, bias);

    float* tail = (out_size >= T_TOK * D_DIM + E_EXP + 1) ? (out + T_TOK * D_DIM) : nullptr;
    stats_kernel<<<1, 32>>>(tail);

    // gate+up: routed z=0..31, shared z=32
    gu_mma<<<dim3(F_DIM / 64, T_TOK / 128, E_EXP + 1), 512, GU_SMEM>>>(x, wg, wu, wsg, wsu);

    // shared down: writes all of out
    dn_mma<true><<<dim3(D_DIM / 128, T_TOK / 128), 512, DN_SMEM>>>(wsd, out);

    // routed down: per-pair rows into g_y
    dn_mma<false><<<dim3(D_DIM / 128, T_TOK / 128, E_EXP), 512, DN_SMEM>>>(wd, out);

    // weighted combine
    combine_kernel<<<T_TOK, 256>>>(out);
}